// round 11
// baseline (speedup 1.0000x reference)
#include <cuda_runtime.h>

#define L_NODES 30000
#define JDIM 64
#define NFEAT 16

// Scratch (allocation-free): per-node tables.
__device__ float g_hXWt[L_NODES * JDIM];
__device__ float g_hXWb[L_NODES * JDIM];

typedef unsigned long long u64;

// ---- packed f32x2 helpers (sm_100+) ----------------------------------------
__device__ __forceinline__ u64 pack2(float lo, float hi) {
    u64 r; asm("mov.b64 %0, {%1, %2};" : "=l"(r) : "f"(lo), "f"(hi)); return r;
}
__device__ __forceinline__ void ffma2(u64& d, u64 a, u64 b) {
    asm("fma.rn.f32x2 %0, %1, %2, %0;" : "+l"(d) : "l"(a), "l"(b));
}
__device__ __forceinline__ float hsum2(u64 v) {
    float lo, hi; asm("mov.b64 {%0, %1}, %2;" : "=f"(lo), "=f"(hi) : "l"(v));
    return lo + hi;
}

// ---------------------------------------------------------------------------
// Prep (measured ~23us; FMA+LDS balanced at 32 warps/SM — leave alone).
// ---------------------------------------------------------------------------
__global__ __launch_bounds__(256, 1) void prep_kernel(
    const float* __restrict__ X,
    const float* __restrict__ h1w,
    const float* __restrict__ h1b,
    const float* __restrict__ g1w)
{
    __shared__ __align__(16) float s_hx[4][64];

    int tid = threadIdx.x;
    int g = tid >> 6;
    int j = tid & 63;

    float wh[16], wt[64], wb[64];
#pragma unroll
    for (int k = 0; k < 16; k++) wh[k] = h1w[k * 64 + j];
#pragma unroll
    for (int k = 0; k < 64; k++) {
        wt[k] = g1w[k * 64 + j];
        wb[k] = g1w[(64 + k) * 64 + j];
    }
    float bj = h1b[j];

    const int NGROUPS = L_NODES / 4;   // 7500
    for (int grp = blockIdx.x; grp < NGROUPS; grp += gridDim.x) {
        int l = grp * 4 + g;

        const float4* xr = (const float4*)(X + l * NFEAT);
        float4 x0 = xr[0], x1 = xr[1], x2 = xr[2], x3 = xr[3];
        float acc = bj;
        acc = fmaf(x0.x, wh[ 0], acc); acc = fmaf(x0.y, wh[ 1], acc);
        acc = fmaf(x0.z, wh[ 2], acc); acc = fmaf(x0.w, wh[ 3], acc);
        acc = fmaf(x1.x, wh[ 4], acc); acc = fmaf(x1.y, wh[ 5], acc);
        acc = fmaf(x1.z, wh[ 6], acc); acc = fmaf(x1.w, wh[ 7], acc);
        acc = fmaf(x2.x, wh[ 8], acc); acc = fmaf(x2.y, wh[ 9], acc);
        acc = fmaf(x2.z, wh[10], acc); acc = fmaf(x2.w, wh[11], acc);
        acc = fmaf(x3.x, wh[12], acc); acc = fmaf(x3.y, wh[13], acc);
        acc = fmaf(x3.z, wh[14], acc); acc = fmaf(x3.w, wh[15], acc);
        s_hx[g][j] = fmaxf(acc, 0.0f);
        __syncthreads();

        float at = 0.0f, ab = 0.0f;
        const float4* vp = (const float4*)s_hx[g];
#pragma unroll
        for (int k4 = 0; k4 < 16; k4++) {
            float4 v = vp[k4];
            int r = 4 * k4;
            at = fmaf(v.x, wt[r + 0], at);  ab = fmaf(v.x, wb[r + 0], ab);
            at = fmaf(v.y, wt[r + 1], at);  ab = fmaf(v.y, wb[r + 1], ab);
            at = fmaf(v.z, wt[r + 2], at);  ab = fmaf(v.z, wb[r + 2], ab);
            at = fmaf(v.w, wt[r + 3], at);  ab = fmaf(v.w, wb[r + 3], ab);
        }
        g_hXWt[l * 64 + j] = at;
        g_hXWb[l * 64 + j] = ab;
        __syncthreads();
    }
}

// ---------------------------------------------------------------------------
// Main: R10 structure (2 nodes/warp, weights amortized in 128 regs) with one
// change: matvec vector reads via LDS.128 (ulonglong2) instead of LDS.64.
// Streaming bytes identical (broadcast cost = words streamed) but LDS
// instruction count and scoreboard waits halve -> more issue slots for the
// FFMA2-dominated stream at 8 warps/SM.
// ---------------------------------------------------------------------------
__global__ __launch_bounds__(256, 1) void ggcn_main_kernel(
    const int*   __restrict__ nbr,
    const float* __restrict__ g1w,
    const float* __restrict__ g1b,
    const float* __restrict__ fw,
    const float* __restrict__ fb,
    float*       __restrict__ out)
{
    __shared__ __align__(16) float s_v[8][2][6][64];   // [warp][node][vec][j]

    int warp = threadIdx.x >> 5;
    int t    = threadIdx.x & 31;
    int l0   = blockIdx.x * 16 + warp * 2;
    int l1   = l0 + 1;

    // Wb columns t, t+32 packed over k-pairs (shared by both nodes).
    u64 wlo[32], whi[32];
#pragma unroll
    for (int k2 = 0; k2 < 32; k2++) {
        wlo[k2] = pack2(g1w[(64 + 2 * k2) * 64 + t],
                        g1w[(64 + 2 * k2 + 1) * 64 + t]);
        whi[k2] = pack2(g1w[(64 + 2 * k2) * 64 + t + 32],
                        g1w[(64 + 2 * k2 + 1) * 64 + t + 32]);
    }
    float blo = g1b[t], bhi = g1b[t + 32];

    int4 nbA = ((const int4*)nbr)[l0];
    int4 nbB = ((const int4*)nbr)[l1];
    int niA[4] = {nbA.x, nbA.y, nbA.z, nbA.w};
    int niB[4] = {nbB.x, nbB.y, nbB.z, nbB.w};

    float A0l[4], A0h[4], A1l[4], A1h[4];
#pragma unroll
    for (int i = 0; i < 4; i++) {
        A0l[i] = g_hXWt[niA[i] * 64 + t];
        A0h[i] = g_hXWt[niA[i] * 64 + t + 32];
        A1l[i] = g_hXWt[niB[i] * 64 + t];
        A1h[i] = g_hXWt[niB[i] * 64 + t + 32];
    }
    float hx0l = g_hXWt[l0 * 64 + t], hx0h = g_hXWt[l0 * 64 + t + 32];
    float hx1l = g_hXWt[l1 * 64 + t], hx1h = g_hXWt[l1 * 64 + t + 32];

    // ---- pairs (B values scoped here so their registers die early) ----
    const int PA[6] = {0, 0, 0, 1, 1, 2};
    const int PB[6] = {1, 2, 3, 2, 3, 3};
    {
        float B0l[4], B0h[4], B1l[4], B1h[4];
#pragma unroll
        for (int i = 0; i < 4; i++) {
            B0l[i] = g_hXWb[niA[i] * 64 + t];
            B0h[i] = g_hXWb[niA[i] * 64 + t + 32];
            B1l[i] = g_hXWb[niB[i] * 64 + t];
            B1h[i] = g_hXWb[niB[i] * 64 + t + 32];
        }
#pragma unroll
        for (int p = 0; p < 6; p++) {
            int i0 = PA[p], i1 = PB[p];
            s_v[warp][0][p][t] =
                0.5f * (fmaxf(A0l[i0] + B0l[i1] + blo, 0.0f) +
                        fmaxf(A0l[i1] + B0l[i0] + blo, 0.0f));
            s_v[warp][0][p][t + 32] =
                0.5f * (fmaxf(A0h[i0] + B0h[i1] + bhi, 0.0f) +
                        fmaxf(A0h[i1] + B0h[i0] + bhi, 0.0f));
            s_v[warp][1][p][t] =
                0.5f * (fmaxf(A1l[i0] + B1l[i1] + blo, 0.0f) +
                        fmaxf(A1l[i1] + B1l[i0] + blo, 0.0f));
            s_v[warp][1][p][t + 32] =
                0.5f * (fmaxf(A1h[i0] + B1h[i1] + bhi, 0.0f) +
                        fmaxf(A1h[i1] + B1h[i0] + bhi, 0.0f));
        }
    }
    __syncwarp();

    // ---- PWb = pairf @ Wb : 6 matvecs x 2 nodes, LDS.128 streams ----
    float PWb0l[6], PWb0h[6], PWb1l[6], PWb1h[6];
#pragma unroll
    for (int p = 0; p < 6; p += 2) {
        u64 a0l = 0ull, a0h = 0ull, a1l = 0ull, a1h = 0ull;   // node 0
        u64 c0l = 0ull, c0h = 0ull, c1l = 0ull, c1h = 0ull;   // node 1
        const ulonglong2* v0A = (const ulonglong2*)s_v[warp][0][p];
        const ulonglong2* v1A = (const ulonglong2*)s_v[warp][0][p + 1];
        const ulonglong2* v0B = (const ulonglong2*)s_v[warp][1][p];
        const ulonglong2* v1B = (const ulonglong2*)s_v[warp][1][p + 1];
#pragma unroll
        for (int k4 = 0; k4 < 16; k4++) {
            ulonglong2 VA = v0A[k4], UA = v1A[k4];
            ulonglong2 VB = v0B[k4], UB = v1B[k4];
            int r = 2 * k4;
            ffma2(a0l, wlo[r], VA.x);      ffma2(a0h, whi[r], VA.x);
            ffma2(a0l, wlo[r + 1], VA.y);  ffma2(a0h, whi[r + 1], VA.y);
            ffma2(a1l, wlo[r], UA.x);      ffma2(a1h, whi[r], UA.x);
            ffma2(a1l, wlo[r + 1], UA.y);  ffma2(a1h, whi[r + 1], UA.y);
            ffma2(c0l, wlo[r], VB.x);      ffma2(c0h, whi[r], VB.x);
            ffma2(c0l, wlo[r + 1], VB.y);  ffma2(c0h, whi[r + 1], VB.y);
            ffma2(c1l, wlo[r], UB.x);      ffma2(c1h, whi[r], UB.x);
            ffma2(c1l, wlo[r + 1], UB.y);  ffma2(c1h, whi[r + 1], UB.y);
        }
        PWb0l[p]     = hsum2(a0l);  PWb0h[p]     = hsum2(a0h);
        PWb0l[p + 1] = hsum2(a1l);  PWb0h[p + 1] = hsum2(a1h);
        PWb1l[p]     = hsum2(c0l);  PWb1h[p]     = hsum2(c0h);
        PWb1l[p + 1] = hsum2(c1l);  PWb1h[p + 1] = hsum2(c1h);
    }
    __syncwarp();   // s_v about to be overwritten

    // ---- triples (indexed by missing element m) ----
    const int PIDX[4][4] = {{-1, 0, 1, 2},
                            { 0,-1, 3, 4},
                            { 1, 3,-1, 5},
                            { 2, 4, 5,-1}};
#pragma unroll
    for (int m = 0; m < 4; m++) {
        float s0l = 0.f, s0h = 0.f, s1l = 0.f, s1h = 0.f;
#pragma unroll
        for (int i = 0; i < 4; i++) {
            if (i == m) continue;
            int a = -1, c = -1;
#pragma unroll
            for (int z = 0; z < 4; z++) {
                if (z != m && z != i) { if (a < 0) a = z; else c = z; }
            }
            int pi = PIDX[a][c];
            s0l += fmaxf(A0l[i] + PWb0l[pi] + blo, 0.0f);
            s0h += fmaxf(A0h[i] + PWb0h[pi] + bhi, 0.0f);
            s1l += fmaxf(A1l[i] + PWb1l[pi] + blo, 0.0f);
            s1h += fmaxf(A1h[i] + PWb1h[pi] + bhi, 0.0f);
        }
        s_v[warp][0][m][t]      = s0l * (1.0f / 3.0f);
        s_v[warp][0][m][t + 32] = s0h * (1.0f / 3.0f);
        s_v[warp][1][m][t]      = s1l * (1.0f / 3.0f);
        s_v[warp][1][m][t + 32] = s1h * (1.0f / 3.0f);
    }
    __syncwarp();

    // ---- TWb = triplef @ Wb : 4 matvecs x 2 nodes, LDS.128 streams ----
    float TWb0l[4], TWb0h[4], TWb1l[4], TWb1h[4];
#pragma unroll
    for (int m = 0; m < 4; m += 2) {
        u64 a0l = 0ull, a0h = 0ull, a1l = 0ull, a1h = 0ull;
        u64 c0l = 0ull, c0h = 0ull, c1l = 0ull, c1h = 0ull;
        const ulonglong2* v0A = (const ulonglong2*)s_v[warp][0][m];
        const ulonglong2* v1A = (const ulonglong2*)s_v[warp][0][m + 1];
        const ulonglong2* v0B = (const ulonglong2*)s_v[warp][1][m];
        const ulonglong2* v1B = (const ulonglong2*)s_v[warp][1][m + 1];
#pragma unroll
        for (int k4 = 0; k4 < 16; k4++) {
            ulonglong2 VA = v0A[k4], UA = v1A[k4];
            ulonglong2 VB = v0B[k4], UB = v1B[k4];
            int r = 2 * k4;
            ffma2(a0l, wlo[r], VA.x);      ffma2(a0h, whi[r], VA.x);
            ffma2(a0l, wlo[r + 1], VA.y);  ffma2(a0h, whi[r + 1], VA.y);
            ffma2(a1l, wlo[r], UA.x);      ffma2(a1h, whi[r], UA.x);
            ffma2(a1l, wlo[r + 1], UA.y);  ffma2(a1h, whi[r + 1], UA.y);
            ffma2(c0l, wlo[r], VB.x);      ffma2(c0h, whi[r], VB.x);
            ffma2(c0l, wlo[r + 1], VB.y);  ffma2(c0h, whi[r + 1], VB.y);
            ffma2(c1l, wlo[r], UB.x);      ffma2(c1h, whi[r], UB.x);
            ffma2(c1l, wlo[r + 1], UB.y);  ffma2(c1h, whi[r + 1], UB.y);
        }
        TWb0l[m]     = hsum2(a0l);  TWb0h[m]     = hsum2(a0h);
        TWb0l[m + 1] = hsum2(a1l);  TWb0h[m + 1] = hsum2(a1h);
        TWb1l[m]     = hsum2(c0l);  TWb1h[m]     = hsum2(c0h);
        TWb1l[m + 1] = hsum2(c1l);  TWb1h[m + 1] = hsum2(c1h);
    }
    __syncwarp();   // s_v reused for E

    // ---- quad + E ----
    {
        float q0l = 0.f, q0h = 0.f, q1l = 0.f, q1h = 0.f;
#pragma unroll
        for (int i = 0; i < 4; i++) {
            q0l += fmaxf(A0l[i] + TWb0l[i] + blo, 0.0f);
            q0h += fmaxf(A0h[i] + TWb0h[i] + bhi, 0.0f);
            q1l += fmaxf(A1l[i] + TWb1l[i] + blo, 0.0f);
            q1h += fmaxf(A1h[i] + TWb1h[i] + bhi, 0.0f);
        }
        s_v[warp][0][0][t]      = fmaxf(q0l * 0.25f, 0.0f);
        s_v[warp][0][0][t + 32] = fmaxf(q0h * 0.25f, 0.0f);
        s_v[warp][1][0][t]      = fmaxf(q1l * 0.25f, 0.0f);
        s_v[warp][1][0][t + 32] = fmaxf(q1h * 0.25f, 0.0f);
    }
    __syncwarp();

    // ---- E2 = relu(hxwt + E@Wb + b), both nodes, LDS.128 streams ----
    u64 e0l = 0ull, e0h = 0ull, e1l = 0ull, e1h = 0ull;
    {
        const ulonglong2* vA = (const ulonglong2*)s_v[warp][0][0];
        const ulonglong2* vB = (const ulonglong2*)s_v[warp][1][0];
#pragma unroll
        for (int k4 = 0; k4 < 16; k4++) {
            ulonglong2 a = vA[k4], b = vB[k4];
            int r = 2 * k4;
            ffma2(e0l, wlo[r], a.x);      ffma2(e0h, whi[r], a.x);
            ffma2(e0l, wlo[r + 1], a.y);  ffma2(e0h, whi[r + 1], a.y);
            ffma2(e1l, wlo[r], b.x);      ffma2(e1h, whi[r], b.x);
            ffma2(e1l, wlo[r + 1], b.y);  ffma2(e1h, whi[r + 1], b.y);
        }
    }
    float E20l = fmaxf(hx0l + hsum2(e0l) + blo, 0.0f);
    float E20h = fmaxf(hx0h + hsum2(e0h) + bhi, 0.0f);
    float E21l = fmaxf(hx1l + hsum2(e1l) + blo, 0.0f);
    float E21h = fmaxf(hx1h + hsum2(e1h) + bhi, 0.0f);

    // ---- readout head: y = E2 @ final_w + final_b, shfl butterflies ----
    float fwl0 = fw[t * 2 + 0],        fwl1 = fw[t * 2 + 1];
    float fwh0 = fw[(t + 32) * 2 + 0], fwh1 = fw[(t + 32) * 2 + 1];
    float p0 = E20l * fwl0 + E20h * fwh0;
    float p1 = E20l * fwl1 + E20h * fwh1;
    float q0 = E21l * fwl0 + E21h * fwh0;
    float q1 = E21l * fwl1 + E21h * fwh1;
#pragma unroll
    for (int off = 16; off > 0; off >>= 1) {
        p0 += __shfl_xor_sync(0xffffffffu, p0, off);
        p1 += __shfl_xor_sync(0xffffffffu, p1, off);
        q0 += __shfl_xor_sync(0xffffffffu, q0, off);
        q1 += __shfl_xor_sync(0xffffffffu, q1, off);
    }
    if (t == 0) {
        float2 oA = {p0 + fb[0], p1 + fb[1]};
        float2 oB = {q0 + fb[0], q1 + fb[1]};
        *(float2*)(out + l0 * 2) = oA;
        *(float2*)(out + l1 * 2) = oB;
    }
}

// ---------------------------------------------------------------------------
// kernel_launch: graph-capturable, allocation-free.
// Inputs: X, neighbors, h1_w, h1_b, g1_w, g1_b, final_w, final_b
// ---------------------------------------------------------------------------
extern "C" void kernel_launch(void* const* d_in, const int* in_sizes, int n_in,
                              void* d_out, int out_size)
{
    const float* X    = (const float*)d_in[0];
    const int*   nbr  = (const int*)  d_in[1];
    const float* h1w  = (const float*)d_in[2];
    const float* h1b  = (const float*)d_in[3];
    const float* g1w  = (const float*)d_in[4];
    const float* g1b  = (const float*)d_in[5];
    const float* fw   = (const float*)d_in[6];
    const float* fb   = (const float*)d_in[7];
    float* out = (float*)d_out;

    (void)in_sizes; (void)n_in; (void)out_size;

    prep_kernel<<<592, 256>>>(X, h1w, h1b, g1w);
    ggcn_main_kernel<<<L_NODES / 16, 256>>>(nbr, g1w, g1b, fw, fb, out);
}

// round 12
// speedup vs baseline: 1.1099x; 1.1099x over previous
#include <cuda_runtime.h>

#define L_NODES 30000
#define JDIM 64
#define NFEAT 16

// Scratch (allocation-free): per-node tables.
__device__ float g_hXWt[L_NODES * JDIM];
__device__ float g_hXWb[L_NODES * JDIM];

typedef unsigned long long u64;

// ---- packed f32x2 helpers (sm_100+) ----------------------------------------
__device__ __forceinline__ u64 pack2(float lo, float hi) {
    u64 r; asm("mov.b64 %0, {%1, %2};" : "=l"(r) : "f"(lo), "f"(hi)); return r;
}
__device__ __forceinline__ void ffma2(u64& d, u64 a, u64 b) {
    asm("fma.rn.f32x2 %0, %1, %2, %0;" : "+l"(d) : "l"(a), "l"(b));
}
__device__ __forceinline__ float hsum2(u64 v) {
    float lo, hi; asm("mov.b64 {%0, %1}, %2;" : "=f"(lo), "=f"(hi) : "l"(v));
    return lo + hi;
}

// ---------------------------------------------------------------------------
// Prep: hx = relu(X@h1_w+h1_b); hXWt=hx@Wt; hXWb=hx@Wb.
// R12 change: matvec part uses packed f32x2 (64 FFMA2 instead of 128 FFMA).
// Weight regs unchanged (64 u64 vs 128 f32). Persistent, 296 blocks.
// ---------------------------------------------------------------------------
__global__ __launch_bounds__(256, 1) void prep_kernel(
    const float* __restrict__ X,
    const float* __restrict__ h1w,
    const float* __restrict__ h1b,
    const float* __restrict__ g1w)
{
    __shared__ __align__(16) float s_hx[4][64];

    int tid = threadIdx.x;
    int g = tid >> 6;
    int j = tid & 63;

    float wh[16];
#pragma unroll
    for (int k = 0; k < 16; k++) wh[k] = h1w[k * 64 + j];

    // Wt/Wb column j packed over k-pairs.
    u64 wt2[32], wb2[32];
#pragma unroll
    for (int k2 = 0; k2 < 32; k2++) {
        wt2[k2] = pack2(g1w[(2 * k2) * 64 + j],      g1w[(2 * k2 + 1) * 64 + j]);
        wb2[k2] = pack2(g1w[(64 + 2 * k2) * 64 + j], g1w[(64 + 2 * k2 + 1) * 64 + j]);
    }
    float bj = h1b[j];

    const int NGROUPS = L_NODES / 4;   // 7500
    for (int grp = blockIdx.x; grp < NGROUPS; grp += gridDim.x) {
        int l = grp * 4 + g;

        const float4* xr = (const float4*)(X + l * NFEAT);
        float4 x0 = xr[0], x1 = xr[1], x2 = xr[2], x3 = xr[3];
        float acc = bj;
        acc = fmaf(x0.x, wh[ 0], acc); acc = fmaf(x0.y, wh[ 1], acc);
        acc = fmaf(x0.z, wh[ 2], acc); acc = fmaf(x0.w, wh[ 3], acc);
        acc = fmaf(x1.x, wh[ 4], acc); acc = fmaf(x1.y, wh[ 5], acc);
        acc = fmaf(x1.z, wh[ 6], acc); acc = fmaf(x1.w, wh[ 7], acc);
        acc = fmaf(x2.x, wh[ 8], acc); acc = fmaf(x2.y, wh[ 9], acc);
        acc = fmaf(x2.z, wh[10], acc); acc = fmaf(x2.w, wh[11], acc);
        acc = fmaf(x3.x, wh[12], acc); acc = fmaf(x3.y, wh[13], acc);
        acc = fmaf(x3.z, wh[14], acc); acc = fmaf(x3.w, wh[15], acc);
        s_hx[g][j] = fmaxf(acc, 0.0f);
        __syncthreads();

        u64 at2 = 0ull, ab2 = 0ull;
        const ulonglong2* vp = (const ulonglong2*)s_hx[g];
#pragma unroll
        for (int k4 = 0; k4 < 16; k4++) {
            ulonglong2 v = vp[k4];
            int r = 2 * k4;
            ffma2(at2, wt2[r], v.x);      ffma2(ab2, wb2[r], v.x);
            ffma2(at2, wt2[r + 1], v.y);  ffma2(ab2, wb2[r + 1], v.y);
        }
        g_hXWt[l * 64 + j] = hsum2(at2);
        g_hXWb[l * 64 + j] = hsum2(ab2);
        __syncthreads();
    }
}

// ---------------------------------------------------------------------------
// Main: R11 inner structure (2 nodes/warp, 128 weight regs, LDS.128 streams)
// R12 change: PERSISTENT — grid=148 (1 block/SM), grid-stride over node-pair
// groups, so the ~2K-cycle weight/bias prologue is paid once per SM instead
// of once per wave (x12.7).
// ---------------------------------------------------------------------------
__global__ __launch_bounds__(256, 1) void ggcn_main_kernel(
    const int*   __restrict__ nbr,
    const float* __restrict__ g1w,
    const float* __restrict__ g1b,
    const float* __restrict__ fw,
    const float* __restrict__ fb,
    float*       __restrict__ out)
{
    __shared__ __align__(16) float s_v[8][2][6][64];   // [warp][node][vec][j]

    int warp = threadIdx.x >> 5;
    int t    = threadIdx.x & 31;

    // ---- prologue (once per block) ----
    u64 wlo[32], whi[32];
#pragma unroll
    for (int k2 = 0; k2 < 32; k2++) {
        wlo[k2] = pack2(g1w[(64 + 2 * k2) * 64 + t],
                        g1w[(64 + 2 * k2 + 1) * 64 + t]);
        whi[k2] = pack2(g1w[(64 + 2 * k2) * 64 + t + 32],
                        g1w[(64 + 2 * k2 + 1) * 64 + t + 32]);
    }
    float blo = g1b[t], bhi = g1b[t + 32];
    float fwl0 = fw[t * 2 + 0],        fwl1 = fw[t * 2 + 1];
    float fwh0 = fw[(t + 32) * 2 + 0], fwh1 = fw[(t + 32) * 2 + 1];
    float fb0 = fb[0], fb1 = fb[1];

    const int PA[6] = {0, 0, 0, 1, 1, 2};
    const int PB[6] = {1, 2, 3, 2, 3, 3};
    const int PIDX[4][4] = {{-1, 0, 1, 2},
                            { 0,-1, 3, 4},
                            { 1, 3,-1, 5},
                            { 2, 4, 5,-1}};

    const int NGRP = L_NODES / 16;   // 1875 node-pair groups (16 nodes/block)
    for (int grp = blockIdx.x; grp < NGRP; grp += gridDim.x) {
        int l0 = grp * 16 + warp * 2;
        int l1 = l0 + 1;

        int4 nbA = ((const int4*)nbr)[l0];
        int4 nbB = ((const int4*)nbr)[l1];
        int niA[4] = {nbA.x, nbA.y, nbA.z, nbA.w};
        int niB[4] = {nbB.x, nbB.y, nbB.z, nbB.w};

        float A0l[4], A0h[4], A1l[4], A1h[4];
#pragma unroll
        for (int i = 0; i < 4; i++) {
            A0l[i] = g_hXWt[niA[i] * 64 + t];
            A0h[i] = g_hXWt[niA[i] * 64 + t + 32];
            A1l[i] = g_hXWt[niB[i] * 64 + t];
            A1h[i] = g_hXWt[niB[i] * 64 + t + 32];
        }
        float hx0l = g_hXWt[l0 * 64 + t], hx0h = g_hXWt[l0 * 64 + t + 32];
        float hx1l = g_hXWt[l1 * 64 + t], hx1h = g_hXWt[l1 * 64 + t + 32];

        // ---- pairs ----
        {
            float B0l[4], B0h[4], B1l[4], B1h[4];
#pragma unroll
            for (int i = 0; i < 4; i++) {
                B0l[i] = g_hXWb[niA[i] * 64 + t];
                B0h[i] = g_hXWb[niA[i] * 64 + t + 32];
                B1l[i] = g_hXWb[niB[i] * 64 + t];
                B1h[i] = g_hXWb[niB[i] * 64 + t + 32];
            }
#pragma unroll
            for (int p = 0; p < 6; p++) {
                int i0 = PA[p], i1 = PB[p];
                s_v[warp][0][p][t] =
                    0.5f * (fmaxf(A0l[i0] + B0l[i1] + blo, 0.0f) +
                            fmaxf(A0l[i1] + B0l[i0] + blo, 0.0f));
                s_v[warp][0][p][t + 32] =
                    0.5f * (fmaxf(A0h[i0] + B0h[i1] + bhi, 0.0f) +
                            fmaxf(A0h[i1] + B0h[i0] + bhi, 0.0f));
                s_v[warp][1][p][t] =
                    0.5f * (fmaxf(A1l[i0] + B1l[i1] + blo, 0.0f) +
                            fmaxf(A1l[i1] + B1l[i0] + blo, 0.0f));
                s_v[warp][1][p][t + 32] =
                    0.5f * (fmaxf(A1h[i0] + B1h[i1] + bhi, 0.0f) +
                            fmaxf(A1h[i1] + B1h[i0] + bhi, 0.0f));
            }
        }
        __syncwarp();

        // ---- PWb = pairf @ Wb : 6 matvecs x 2 nodes ----
        float PWb0l[6], PWb0h[6], PWb1l[6], PWb1h[6];
#pragma unroll
        for (int p = 0; p < 6; p += 2) {
            u64 a0l = 0ull, a0h = 0ull, a1l = 0ull, a1h = 0ull;
            u64 c0l = 0ull, c0h = 0ull, c1l = 0ull, c1h = 0ull;
            const ulonglong2* v0A = (const ulonglong2*)s_v[warp][0][p];
            const ulonglong2* v1A = (const ulonglong2*)s_v[warp][0][p + 1];
            const ulonglong2* v0B = (const ulonglong2*)s_v[warp][1][p];
            const ulonglong2* v1B = (const ulonglong2*)s_v[warp][1][p + 1];
#pragma unroll
            for (int k4 = 0; k4 < 16; k4++) {
                ulonglong2 VA = v0A[k4], UA = v1A[k4];
                ulonglong2 VB = v0B[k4], UB = v1B[k4];
                int r = 2 * k4;
                ffma2(a0l, wlo[r], VA.x);      ffma2(a0h, whi[r], VA.x);
                ffma2(a0l, wlo[r + 1], VA.y);  ffma2(a0h, whi[r + 1], VA.y);
                ffma2(a1l, wlo[r], UA.x);      ffma2(a1h, whi[r], UA.x);
                ffma2(a1l, wlo[r + 1], UA.y);  ffma2(a1h, whi[r + 1], UA.y);
                ffma2(c0l, wlo[r], VB.x);      ffma2(c0h, whi[r], VB.x);
                ffma2(c0l, wlo[r + 1], VB.y);  ffma2(c0h, whi[r + 1], VB.y);
                ffma2(c1l, wlo[r], UB.x);      ffma2(c1h, whi[r], UB.x);
                ffma2(c1l, wlo[r + 1], UB.y);  ffma2(c1h, whi[r + 1], UB.y);
            }
            PWb0l[p]     = hsum2(a0l);  PWb0h[p]     = hsum2(a0h);
            PWb0l[p + 1] = hsum2(a1l);  PWb0h[p + 1] = hsum2(a1h);
            PWb1l[p]     = hsum2(c0l);  PWb1h[p]     = hsum2(c0h);
            PWb1l[p + 1] = hsum2(c1l);  PWb1h[p + 1] = hsum2(c1h);
        }
        __syncwarp();

        // ---- triples ----
#pragma unroll
        for (int m = 0; m < 4; m++) {
            float s0l = 0.f, s0h = 0.f, s1l = 0.f, s1h = 0.f;
#pragma unroll
            for (int i = 0; i < 4; i++) {
                if (i == m) continue;
                int a = -1, c = -1;
#pragma unroll
                for (int z = 0; z < 4; z++) {
                    if (z != m && z != i) { if (a < 0) a = z; else c = z; }
                }
                int pi = PIDX[a][c];
                s0l += fmaxf(A0l[i] + PWb0l[pi] + blo, 0.0f);
                s0h += fmaxf(A0h[i] + PWb0h[pi] + bhi, 0.0f);
                s1l += fmaxf(A1l[i] + PWb1l[pi] + blo, 0.0f);
                s1h += fmaxf(A1h[i] + PWb1h[pi] + bhi, 0.0f);
            }
            s_v[warp][0][m][t]      = s0l * (1.0f / 3.0f);
            s_v[warp][0][m][t + 32] = s0h * (1.0f / 3.0f);
            s_v[warp][1][m][t]      = s1l * (1.0f / 3.0f);
            s_v[warp][1][m][t + 32] = s1h * (1.0f / 3.0f);
        }
        __syncwarp();

        // ---- TWb = triplef @ Wb : 4 matvecs x 2 nodes ----
        float TWb0l[4], TWb0h[4], TWb1l[4], TWb1h[4];
#pragma unroll
        for (int m = 0; m < 4; m += 2) {
            u64 a0l = 0ull, a0h = 0ull, a1l = 0ull, a1h = 0ull;
            u64 c0l = 0ull, c0h = 0ull, c1l = 0ull, c1h = 0ull;
            const ulonglong2* v0A = (const ulonglong2*)s_v[warp][0][m];
            const ulonglong2* v1A = (const ulonglong2*)s_v[warp][0][m + 1];
            const ulonglong2* v0B = (const ulonglong2*)s_v[warp][1][m];
            const ulonglong2* v1B = (const ulonglong2*)s_v[warp][1][m + 1];
#pragma unroll
            for (int k4 = 0; k4 < 16; k4++) {
                ulonglong2 VA = v0A[k4], UA = v1A[k4];
                ulonglong2 VB = v0B[k4], UB = v1B[k4];
                int r = 2 * k4;
                ffma2(a0l, wlo[r], VA.x);      ffma2(a0h, whi[r], VA.x);
                ffma2(a0l, wlo[r + 1], VA.y);  ffma2(a0h, whi[r + 1], VA.y);
                ffma2(a1l, wlo[r], UA.x);      ffma2(a1h, whi[r], UA.x);
                ffma2(a1l, wlo[r + 1], UA.y);  ffma2(a1h, whi[r + 1], UA.y);
                ffma2(c0l, wlo[r], VB.x);      ffma2(c0h, whi[r], VB.x);
                ffma2(c0l, wlo[r + 1], VB.y);  ffma2(c0h, whi[r + 1], VB.y);
                ffma2(c1l, wlo[r], UB.x);      ffma2(c1h, whi[r], UB.x);
                ffma2(c1l, wlo[r + 1], UB.y);  ffma2(c1h, whi[r + 1], UB.y);
            }
            TWb0l[m]     = hsum2(a0l);  TWb0h[m]     = hsum2(a0h);
            TWb0l[m + 1] = hsum2(a1l);  TWb0h[m + 1] = hsum2(a1h);
            TWb1l[m]     = hsum2(c0l);  TWb1h[m]     = hsum2(c0h);
            TWb1l[m + 1] = hsum2(c1l);  TWb1h[m + 1] = hsum2(c1h);
        }
        __syncwarp();

        // ---- quad + E ----
        {
            float q0l = 0.f, q0h = 0.f, q1l = 0.f, q1h = 0.f;
#pragma unroll
            for (int i = 0; i < 4; i++) {
                q0l += fmaxf(A0l[i] + TWb0l[i] + blo, 0.0f);
                q0h += fmaxf(A0h[i] + TWb0h[i] + bhi, 0.0f);
                q1l += fmaxf(A1l[i] + TWb1l[i] + blo, 0.0f);
                q1h += fmaxf(A1h[i] + TWb1h[i] + bhi, 0.0f);
            }
            s_v[warp][0][0][t]      = fmaxf(q0l * 0.25f, 0.0f);
            s_v[warp][0][0][t + 32] = fmaxf(q0h * 0.25f, 0.0f);
            s_v[warp][1][0][t]      = fmaxf(q1l * 0.25f, 0.0f);
            s_v[warp][1][0][t + 32] = fmaxf(q1h * 0.25f, 0.0f);
        }
        __syncwarp();

        // ---- E2 = relu(hxwt + E@Wb + b) ----
        u64 e0l = 0ull, e0h = 0ull, e1l = 0ull, e1h = 0ull;
        {
            const ulonglong2* vA = (const ulonglong2*)s_v[warp][0][0];
            const ulonglong2* vB = (const ulonglong2*)s_v[warp][1][0];
#pragma unroll
            for (int k4 = 0; k4 < 16; k4++) {
                ulonglong2 a = vA[k4], b = vB[k4];
                int r = 2 * k4;
                ffma2(e0l, wlo[r], a.x);      ffma2(e0h, whi[r], a.x);
                ffma2(e0l, wlo[r + 1], a.y);  ffma2(e0h, whi[r + 1], a.y);
                ffma2(e1l, wlo[r], b.x);      ffma2(e1h, whi[r], b.x);
                ffma2(e1l, wlo[r + 1], b.y);  ffma2(e1h, whi[r + 1], b.y);
            }
        }
        float E20l = fmaxf(hx0l + hsum2(e0l) + blo, 0.0f);
        float E20h = fmaxf(hx0h + hsum2(e0h) + bhi, 0.0f);
        float E21l = fmaxf(hx1l + hsum2(e1l) + blo, 0.0f);
        float E21h = fmaxf(hx1h + hsum2(e1h) + bhi, 0.0f);

        // ---- readout head ----
        float p0 = E20l * fwl0 + E20h * fwh0;
        float p1 = E20l * fwl1 + E20h * fwh1;
        float q0 = E21l * fwl0 + E21h * fwh0;
        float q1 = E21l * fwl1 + E21h * fwh1;
#pragma unroll
        for (int off = 16; off > 0; off >>= 1) {
            p0 += __shfl_xor_sync(0xffffffffu, p0, off);
            p1 += __shfl_xor_sync(0xffffffffu, p1, off);
            q0 += __shfl_xor_sync(0xffffffffu, q0, off);
            q1 += __shfl_xor_sync(0xffffffffu, q1, off);
        }
        if (t == 0) {
            float2 oA = {p0 + fb0, p1 + fb1};
            float2 oB = {q0 + fb0, q1 + fb1};
            *(float2*)(out + l0 * 2) = oA;
            *(float2*)(out + l1 * 2) = oB;
        }
        __syncwarp();   // protect s_v reuse across loop iterations
    }
}

// ---------------------------------------------------------------------------
// kernel_launch: graph-capturable, allocation-free.
// Inputs: X, neighbors, h1_w, h1_b, g1_w, g1_b, final_w, final_b
// ---------------------------------------------------------------------------
extern "C" void kernel_launch(void* const* d_in, const int* in_sizes, int n_in,
                              void* d_out, int out_size)
{
    const float* X    = (const float*)d_in[0];
    const int*   nbr  = (const int*)  d_in[1];
    const float* h1w  = (const float*)d_in[2];
    const float* h1b  = (const float*)d_in[3];
    const float* g1w  = (const float*)d_in[4];
    const float* g1b  = (const float*)d_in[5];
    const float* fw   = (const float*)d_in[6];
    const float* fb   = (const float*)d_in[7];
    float* out = (float*)d_out;

    (void)in_sizes; (void)n_in; (void)out_size;

    prep_kernel<<<296, 256>>>(X, h1w, h1b, g1w);
    ggcn_main_kernel<<<148, 256>>>(nbr, g1w, g1b, fw, fb, out);
}

// round 13
// speedup vs baseline: 1.1170x; 1.0064x over previous
#include <cuda_runtime.h>

#define L_NODES 30000
#define JDIM 64
#define NFEAT 16

// Scratch (allocation-free): per-node tables.
__device__ float g_hXWt[L_NODES * JDIM];
__device__ float g_hXWb[L_NODES * JDIM];

typedef unsigned long long u64;

// ---- packed f32x2 helpers (sm_100+) ----------------------------------------
__device__ __forceinline__ u64 pack2(float lo, float hi) {
    u64 r; asm("mov.b64 %0, {%1, %2};" : "=l"(r) : "f"(lo), "f"(hi)); return r;
}
__device__ __forceinline__ void ffma2(u64& d, u64 a, u64 b) {
    asm("fma.rn.f32x2 %0, %1, %2, %0;" : "+l"(d) : "l"(a), "l"(b));
}
__device__ __forceinline__ float hsum2(u64 v) {
    float lo, hi; asm("mov.b64 {%0, %1}, %2;" : "=f"(lo), "=f"(hi) : "l"(v));
    return lo + hi;
}

// ---------------------------------------------------------------------------
// Prep (unchanged from R12; ~15us, LSU-bound on the hx broadcast — left alone).
// ---------------------------------------------------------------------------
__global__ __launch_bounds__(256, 1) void prep_kernel(
    const float* __restrict__ X,
    const float* __restrict__ h1w,
    const float* __restrict__ h1b,
    const float* __restrict__ g1w)
{
    __shared__ __align__(16) float s_hx[4][64];

    int tid = threadIdx.x;
    int g = tid >> 6;
    int j = tid & 63;

    float wh[16];
#pragma unroll
    for (int k = 0; k < 16; k++) wh[k] = h1w[k * 64 + j];

    u64 wt2[32], wb2[32];
#pragma unroll
    for (int k2 = 0; k2 < 32; k2++) {
        wt2[k2] = pack2(g1w[(2 * k2) * 64 + j],      g1w[(2 * k2 + 1) * 64 + j]);
        wb2[k2] = pack2(g1w[(64 + 2 * k2) * 64 + j], g1w[(64 + 2 * k2 + 1) * 64 + j]);
    }
    float bj = h1b[j];

    const int NGROUPS = L_NODES / 4;   // 7500
    for (int grp = blockIdx.x; grp < NGROUPS; grp += gridDim.x) {
        int l = grp * 4 + g;

        const float4* xr = (const float4*)(X + l * NFEAT);
        float4 x0 = xr[0], x1 = xr[1], x2 = xr[2], x3 = xr[3];
        float acc = bj;
        acc = fmaf(x0.x, wh[ 0], acc); acc = fmaf(x0.y, wh[ 1], acc);
        acc = fmaf(x0.z, wh[ 2], acc); acc = fmaf(x0.w, wh[ 3], acc);
        acc = fmaf(x1.x, wh[ 4], acc); acc = fmaf(x1.y, wh[ 5], acc);
        acc = fmaf(x1.z, wh[ 6], acc); acc = fmaf(x1.w, wh[ 7], acc);
        acc = fmaf(x2.x, wh[ 8], acc); acc = fmaf(x2.y, wh[ 9], acc);
        acc = fmaf(x2.z, wh[10], acc); acc = fmaf(x2.w, wh[11], acc);
        acc = fmaf(x3.x, wh[12], acc); acc = fmaf(x3.y, wh[13], acc);
        acc = fmaf(x3.z, wh[14], acc); acc = fmaf(x3.w, wh[15], acc);
        s_hx[g][j] = fmaxf(acc, 0.0f);
        __syncthreads();

        u64 at2 = 0ull, ab2 = 0ull;
        const ulonglong2* vp = (const ulonglong2*)s_hx[g];
#pragma unroll
        for (int k4 = 0; k4 < 16; k4++) {
            ulonglong2 v = vp[k4];
            int r = 2 * k4;
            ffma2(at2, wt2[r], v.x);      ffma2(ab2, wb2[r], v.x);
            ffma2(at2, wt2[r + 1], v.y);  ffma2(ab2, wb2[r + 1], v.y);
        }
        g_hXWt[l * 64 + j] = hsum2(at2);
        g_hXWb[l * 64 + j] = hsum2(ab2);
        __syncthreads();
    }
}

// ---------------------------------------------------------------------------
// Main (R13): persistent, 2 nodes/warp, 128 weight regs. Changes vs R12:
//  - Aib = A + b precomputed (reused by pairs/triples/quad).
//  - PWb fused into triples via complement pairs: PWb values consumed
//    immediately after hsum2, never stored (PWb/TWb arrays eliminated,
//    ~40 fewer live registers -> deeper LDS hoisting by ptxas).
//  - TWb fused into quad the same way.
// Arithmetic identical up to add-association.
// ---------------------------------------------------------------------------
__global__ __launch_bounds__(256, 1) void ggcn_main_kernel(
    const int*   __restrict__ nbr,
    const float* __restrict__ g1w,
    const float* __restrict__ g1b,
    const float* __restrict__ fw,
    const float* __restrict__ fb,
    float*       __restrict__ out)
{
    __shared__ __align__(16) float s_v[8][2][6][64];   // [warp][node][vec][j]

    int warp = threadIdx.x >> 5;
    int t    = threadIdx.x & 31;

    // ---- prologue (once per block) ----
    u64 wlo[32], whi[32];
#pragma unroll
    for (int k2 = 0; k2 < 32; k2++) {
        wlo[k2] = pack2(g1w[(64 + 2 * k2) * 64 + t],
                        g1w[(64 + 2 * k2 + 1) * 64 + t]);
        whi[k2] = pack2(g1w[(64 + 2 * k2) * 64 + t + 32],
                        g1w[(64 + 2 * k2 + 1) * 64 + t + 32]);
    }
    float blo = g1b[t], bhi = g1b[t + 32];
    float fwl0 = fw[t * 2 + 0],        fwl1 = fw[t * 2 + 1];
    float fwh0 = fw[(t + 32) * 2 + 0], fwh1 = fw[(t + 32) * 2 + 1];
    float fb0 = fb[0], fb1 = fb[1];

    // pair index p -> members; complement tables for fusion.
    const int PA[6] = {0, 0, 0, 1, 1, 2};
    const int PB[6] = {1, 2, 3, 2, 3, 3};
    // cp loop processes pair CP1[cp] together with its complement CP2[cp].
    const int CP1[3] = {0, 1, 2};      // pairs {0,1},{0,2},{0,3}
    const int CP2[3] = {5, 4, 3};      // pairs {2,3},{1,3},{1,2}
    const int C1A[3] = {2, 1, 1};      // complement members of CP1
    const int C1B[3] = {3, 3, 2};
    const int C2A[3] = {0, 0, 0};      // complement members of CP2
    const int C2B[3] = {1, 2, 3};

    const int NGRP = L_NODES / 16;   // 1875 node-pair groups
    for (int grp = blockIdx.x; grp < NGRP; grp += gridDim.x) {
        int l0 = grp * 16 + warp * 2;
        int l1 = l0 + 1;

        int4 nbA = ((const int4*)nbr)[l0];
        int4 nbB = ((const int4*)nbr)[l1];
        int niA[4] = {nbA.x, nbA.y, nbA.z, nbA.w};
        int niB[4] = {nbB.x, nbB.y, nbB.z, nbB.w};

        // Aib = A + b (bias folded once)
        float Aib0l[4], Aib0h[4], Aib1l[4], Aib1h[4];
#pragma unroll
        for (int i = 0; i < 4; i++) {
            Aib0l[i] = g_hXWt[niA[i] * 64 + t]      + blo;
            Aib0h[i] = g_hXWt[niA[i] * 64 + t + 32] + bhi;
            Aib1l[i] = g_hXWt[niB[i] * 64 + t]      + blo;
            Aib1h[i] = g_hXWt[niB[i] * 64 + t + 32] + bhi;
        }
        float hx0l = g_hXWt[l0 * 64 + t], hx0h = g_hXWt[l0 * 64 + t + 32];
        float hx1l = g_hXWt[l1 * 64 + t], hx1h = g_hXWt[l1 * 64 + t + 32];

        // ---- pairs (B scoped; dies here) ----
        {
            float B0l[4], B0h[4], B1l[4], B1h[4];
#pragma unroll
            for (int i = 0; i < 4; i++) {
                B0l[i] = g_hXWb[niA[i] * 64 + t];
                B0h[i] = g_hXWb[niA[i] * 64 + t + 32];
                B1l[i] = g_hXWb[niB[i] * 64 + t];
                B1h[i] = g_hXWb[niB[i] * 64 + t + 32];
            }
#pragma unroll
            for (int p = 0; p < 6; p++) {
                int i0 = PA[p], i1 = PB[p];
                s_v[warp][0][p][t] =
                    0.5f * (fmaxf(Aib0l[i0] + B0l[i1], 0.0f) +
                            fmaxf(Aib0l[i1] + B0l[i0], 0.0f));
                s_v[warp][0][p][t + 32] =
                    0.5f * (fmaxf(Aib0h[i0] + B0h[i1], 0.0f) +
                            fmaxf(Aib0h[i1] + B0h[i0], 0.0f));
                s_v[warp][1][p][t] =
                    0.5f * (fmaxf(Aib1l[i0] + B1l[i1], 0.0f) +
                            fmaxf(Aib1l[i1] + B1l[i0], 0.0f));
                s_v[warp][1][p][t + 32] =
                    0.5f * (fmaxf(Aib1h[i0] + B1h[i1], 0.0f) +
                            fmaxf(Aib1h[i1] + B1h[i0], 0.0f));
            }
        }
        __syncwarp();

        // ---- fused PWb matvecs + triple accumulation ----
        float tr0l[4] = {0.f, 0.f, 0.f, 0.f}, tr0h[4] = {0.f, 0.f, 0.f, 0.f};
        float tr1l[4] = {0.f, 0.f, 0.f, 0.f}, tr1h[4] = {0.f, 0.f, 0.f, 0.f};
#pragma unroll
        for (int cp = 0; cp < 3; cp++) {
            int p = CP1[cp], q = CP2[cp];
            u64 a0l = 0ull, a0h = 0ull, a1l = 0ull, a1h = 0ull;   // pair p, n0/n1
            u64 c0l = 0ull, c0h = 0ull, c1l = 0ull, c1h = 0ull;   // pair q, n0/n1
            const ulonglong2* vP0 = (const ulonglong2*)s_v[warp][0][p];
            const ulonglong2* vQ0 = (const ulonglong2*)s_v[warp][0][q];
            const ulonglong2* vP1 = (const ulonglong2*)s_v[warp][1][p];
            const ulonglong2* vQ1 = (const ulonglong2*)s_v[warp][1][q];
#pragma unroll
            for (int k4 = 0; k4 < 16; k4++) {
                ulonglong2 P0 = vP0[k4], Q0 = vQ0[k4];
                ulonglong2 P1 = vP1[k4], Q1 = vQ1[k4];
                int r = 2 * k4;
                ffma2(a0l, wlo[r], P0.x);      ffma2(a0h, whi[r], P0.x);
                ffma2(a0l, wlo[r + 1], P0.y);  ffma2(a0h, whi[r + 1], P0.y);
                ffma2(c0l, wlo[r], Q0.x);      ffma2(c0h, whi[r], Q0.x);
                ffma2(c0l, wlo[r + 1], Q0.y);  ffma2(c0h, whi[r + 1], Q0.y);
                ffma2(a1l, wlo[r], P1.x);      ffma2(a1h, whi[r], P1.x);
                ffma2(a1l, wlo[r + 1], P1.y);  ffma2(a1h, whi[r + 1], P1.y);
                ffma2(c1l, wlo[r], Q1.x);      ffma2(c1h, whi[r], Q1.x);
                ffma2(c1l, wlo[r + 1], Q1.y);  ffma2(c1h, whi[r + 1], Q1.y);
            }
            float pw0l = hsum2(a0l), pw0h = hsum2(a0h);
            float qw0l = hsum2(c0l), qw0h = hsum2(c0h);
            float pw1l = hsum2(a1l), pw1h = hsum2(a1h);
            float qw1l = hsum2(c1l), qw1h = hsum2(c1h);

            int u = C1A[cp], v = C1B[cp];   // PWb[p] feeds triples u,v
            int x = C2A[cp], y = C2B[cp];   // PWb[q] feeds triples x,y
            tr0l[u] += fmaxf(Aib0l[v] + pw0l, 0.0f);
            tr0l[v] += fmaxf(Aib0l[u] + pw0l, 0.0f);
            tr0h[u] += fmaxf(Aib0h[v] + pw0h, 0.0f);
            tr0h[v] += fmaxf(Aib0h[u] + pw0h, 0.0f);
            tr0l[x] += fmaxf(Aib0l[y] + qw0l, 0.0f);
            tr0l[y] += fmaxf(Aib0l[x] + qw0l, 0.0f);
            tr0h[x] += fmaxf(Aib0h[y] + qw0h, 0.0f);
            tr0h[y] += fmaxf(Aib0h[x] + qw0h, 0.0f);
            tr1l[u] += fmaxf(Aib1l[v] + pw1l, 0.0f);
            tr1l[v] += fmaxf(Aib1l[u] + pw1l, 0.0f);
            tr1h[u] += fmaxf(Aib1h[v] + pw1h, 0.0f);
            tr1h[v] += fmaxf(Aib1h[u] + pw1h, 0.0f);
            tr1l[x] += fmaxf(Aib1l[y] + qw1l, 0.0f);
            tr1l[y] += fmaxf(Aib1l[x] + qw1l, 0.0f);
            tr1h[x] += fmaxf(Aib1h[y] + qw1h, 0.0f);
            tr1h[y] += fmaxf(Aib1h[x] + qw1h, 0.0f);
        }
        __syncwarp();   // all lanes done reading pair vectors

        // ---- stage triple vectors ----
#pragma unroll
        for (int m = 0; m < 4; m++) {
            s_v[warp][0][m][t]      = tr0l[m] * (1.0f / 3.0f);
            s_v[warp][0][m][t + 32] = tr0h[m] * (1.0f / 3.0f);
            s_v[warp][1][m][t]      = tr1l[m] * (1.0f / 3.0f);
            s_v[warp][1][m][t + 32] = tr1h[m] * (1.0f / 3.0f);
        }
        __syncwarp();

        // ---- fused TWb matvecs + quad accumulation ----
        float q0l = 0.f, q0h = 0.f, q1l = 0.f, q1h = 0.f;
#pragma unroll
        for (int m = 0; m < 4; m += 2) {
            u64 a0l = 0ull, a0h = 0ull, a1l = 0ull, a1h = 0ull;
            u64 c0l = 0ull, c0h = 0ull, c1l = 0ull, c1h = 0ull;
            const ulonglong2* v0A = (const ulonglong2*)s_v[warp][0][m];
            const ulonglong2* v1A = (const ulonglong2*)s_v[warp][0][m + 1];
            const ulonglong2* v0B = (const ulonglong2*)s_v[warp][1][m];
            const ulonglong2* v1B = (const ulonglong2*)s_v[warp][1][m + 1];
#pragma unroll
            for (int k4 = 0; k4 < 16; k4++) {
                ulonglong2 VA = v0A[k4], UA = v1A[k4];
                ulonglong2 VB = v0B[k4], UB = v1B[k4];
                int r = 2 * k4;
                ffma2(a0l, wlo[r], VA.x);      ffma2(a0h, whi[r], VA.x);
                ffma2(a0l, wlo[r + 1], VA.y);  ffma2(a0h, whi[r + 1], VA.y);
                ffma2(a1l, wlo[r], UA.x);      ffma2(a1h, whi[r], UA.x);
                ffma2(a1l, wlo[r + 1], UA.y);  ffma2(a1h, whi[r + 1], UA.y);
                ffma2(c0l, wlo[r], VB.x);      ffma2(c0h, whi[r], VB.x);
                ffma2(c0l, wlo[r + 1], VB.y);  ffma2(c0h, whi[r + 1], VB.y);
                ffma2(c1l, wlo[r], UB.x);      ffma2(c1h, whi[r], UB.x);
                ffma2(c1l, wlo[r + 1], UB.y);  ffma2(c1h, whi[r + 1], UB.y);
            }
            // TWb values consumed immediately into quad sums
            q0l += fmaxf(Aib0l[m] + hsum2(a0l), 0.0f)
                 + fmaxf(Aib0l[m + 1] + hsum2(a1l), 0.0f);
            q0h += fmaxf(Aib0h[m] + hsum2(a0h), 0.0f)
                 + fmaxf(Aib0h[m + 1] + hsum2(a1h), 0.0f);
            q1l += fmaxf(Aib1l[m] + hsum2(c0l), 0.0f)
                 + fmaxf(Aib1l[m + 1] + hsum2(c1l), 0.0f);
            q1h += fmaxf(Aib1h[m] + hsum2(c0h), 0.0f)
                 + fmaxf(Aib1h[m + 1] + hsum2(c1h), 0.0f);
        }
        __syncwarp();   // all lanes done reading triple vectors

        // ---- E vector ----
        s_v[warp][0][0][t]      = fmaxf(q0l * 0.25f, 0.0f);
        s_v[warp][0][0][t + 32] = fmaxf(q0h * 0.25f, 0.0f);
        s_v[warp][1][0][t]      = fmaxf(q1l * 0.25f, 0.0f);
        s_v[warp][1][0][t + 32] = fmaxf(q1h * 0.25f, 0.0f);
        __syncwarp();

        // ---- E2 = relu(hxwt + E@Wb + b) ----
        u64 e0l = 0ull, e0h = 0ull, e1l = 0ull, e1h = 0ull;
        {
            const ulonglong2* vA = (const ulonglong2*)s_v[warp][0][0];
            const ulonglong2* vB = (const ulonglong2*)s_v[warp][1][0];
#pragma unroll
            for (int k4 = 0; k4 < 16; k4++) {
                ulonglong2 a = vA[k4], b = vB[k4];
                int r = 2 * k4;
                ffma2(e0l, wlo[r], a.x);      ffma2(e0h, whi[r], a.x);
                ffma2(e0l, wlo[r + 1], a.y);  ffma2(e0h, whi[r + 1], a.y);
                ffma2(e1l, wlo[r], b.x);      ffma2(e1h, whi[r], b.x);
                ffma2(e1l, wlo[r + 1], b.y);  ffma2(e1h, whi[r + 1], b.y);
            }
        }
        float E20l = fmaxf(hx0l + hsum2(e0l) + blo, 0.0f);
        float E20h = fmaxf(hx0h + hsum2(e0h) + bhi, 0.0f);
        float E21l = fmaxf(hx1l + hsum2(e1l) + blo, 0.0f);
        float E21h = fmaxf(hx1h + hsum2(e1h) + bhi, 0.0f);

        // ---- readout head ----
        float p0 = E20l * fwl0 + E20h * fwh0;
        float p1 = E20l * fwl1 + E20h * fwh1;
        float r0 = E21l * fwl0 + E21h * fwh0;
        float r1 = E21l * fwl1 + E21h * fwh1;
#pragma unroll
        for (int off = 16; off > 0; off >>= 1) {
            p0 += __shfl_xor_sync(0xffffffffu, p0, off);
            p1 += __shfl_xor_sync(0xffffffffu, p1, off);
            r0 += __shfl_xor_sync(0xffffffffu, r0, off);
            r1 += __shfl_xor_sync(0xffffffffu, r1, off);
        }
        if (t == 0) {
            float2 oA = {p0 + fb0, p1 + fb1};
            float2 oB = {r0 + fb0, r1 + fb1};
            *(float2*)(out + l0 * 2) = oA;
            *(float2*)(out + l1 * 2) = oB;
        }
        __syncwarp();   // protect s_v reuse across loop iterations
    }
}

// ---------------------------------------------------------------------------
// kernel_launch: graph-capturable, allocation-free.
// Inputs: X, neighbors, h1_w, h1_b, g1_w, g1_b, final_w, final_b
// ---------------------------------------------------------------------------
extern "C" void kernel_launch(void* const* d_in, const int* in_sizes, int n_in,
                              void* d_out, int out_size)
{
    const float* X    = (const float*)d_in[0];
    const int*   nbr  = (const int*)  d_in[1];
    const float* h1w  = (const float*)d_in[2];
    const float* h1b  = (const float*)d_in[3];
    const float* g1w  = (const float*)d_in[4];
    const float* g1b  = (const float*)d_in[5];
    const float* fw   = (const float*)d_in[6];
    const float* fb   = (const float*)d_in[7];
    float* out = (float*)d_out;

    (void)in_sizes; (void)n_in; (void)out_size;

    prep_kernel<<<296, 256>>>(X, h1w, h1b, g1w);
    ggcn_main_kernel<<<148, 256>>>(nbr, g1w, g1b, fw, fb, out);
}

// round 15
// speedup vs baseline: 1.1323x; 1.0137x over previous
#include <cuda_runtime.h>

// R15 = R14 resubmitted unchanged: R14 bench died on container infra (twice),
// kernel never executed. No evidence to update on.

#define L_NODES 30000
#define JDIM 64
#define NFEAT 16

// Scratch (allocation-free): per-node tables.
__device__ float g_hXWt[L_NODES * JDIM];
__device__ float g_hXWb[L_NODES * JDIM];

typedef unsigned long long u64;

// ---- packed f32x2 helpers (sm_100+) ----------------------------------------
__device__ __forceinline__ u64 pack2(float lo, float hi) {
    u64 r; asm("mov.b64 %0, {%1, %2};" : "=l"(r) : "f"(lo), "f"(hi)); return r;
}
__device__ __forceinline__ void ffma2(u64& d, u64 a, u64 b) {
    asm("fma.rn.f32x2 %0, %1, %2, %0;" : "+l"(d) : "l"(a), "l"(b));
}
__device__ __forceinline__ float hsum2(u64 v) {
    float lo, hi; asm("mov.b64 {%0, %1}, %2;" : "=f"(lo), "=f"(hi) : "l"(v));
    return lo + hi;
}

// ---------------------------------------------------------------------------
// Prep (unchanged; ~15-18us, LSU-bound on the hx broadcast).
// ---------------------------------------------------------------------------
__global__ __launch_bounds__(256, 1) void prep_kernel(
    const float* __restrict__ X,
    const float* __restrict__ h1w,
    const float* __restrict__ h1b,
    const float* __restrict__ g1w)
{
    __shared__ __align__(16) float s_hx[4][64];

    int tid = threadIdx.x;
    int g = tid >> 6;
    int j = tid & 63;

    float wh[16];
#pragma unroll
    for (int k = 0; k < 16; k++) wh[k] = h1w[k * 64 + j];

    u64 wt2[32], wb2[32];
#pragma unroll
    for (int k2 = 0; k2 < 32; k2++) {
        wt2[k2] = pack2(g1w[(2 * k2) * 64 + j],      g1w[(2 * k2 + 1) * 64 + j]);
        wb2[k2] = pack2(g1w[(64 + 2 * k2) * 64 + j], g1w[(64 + 2 * k2 + 1) * 64 + j]);
    }
    float bj = h1b[j];

    const int NGROUPS = L_NODES / 4;   // 7500
    for (int grp = blockIdx.x; grp < NGROUPS; grp += gridDim.x) {
        int l = grp * 4 + g;

        const float4* xr = (const float4*)(X + l * NFEAT);
        float4 x0 = xr[0], x1 = xr[1], x2 = xr[2], x3 = xr[3];
        float acc = bj;
        acc = fmaf(x0.x, wh[ 0], acc); acc = fmaf(x0.y, wh[ 1], acc);
        acc = fmaf(x0.z, wh[ 2], acc); acc = fmaf(x0.w, wh[ 3], acc);
        acc = fmaf(x1.x, wh[ 4], acc); acc = fmaf(x1.y, wh[ 5], acc);
        acc = fmaf(x1.z, wh[ 6], acc); acc = fmaf(x1.w, wh[ 7], acc);
        acc = fmaf(x2.x, wh[ 8], acc); acc = fmaf(x2.y, wh[ 9], acc);
        acc = fmaf(x2.z, wh[10], acc); acc = fmaf(x2.w, wh[11], acc);
        acc = fmaf(x3.x, wh[12], acc); acc = fmaf(x3.y, wh[13], acc);
        acc = fmaf(x3.z, wh[14], acc); acc = fmaf(x3.w, wh[15], acc);
        s_hx[g][j] = fmaxf(acc, 0.0f);
        __syncthreads();

        u64 at2 = 0ull, ab2 = 0ull;
        const ulonglong2* vp = (const ulonglong2*)s_hx[g];
#pragma unroll
        for (int k4 = 0; k4 < 16; k4++) {
            ulonglong2 v = vp[k4];
            int r = 2 * k4;
            ffma2(at2, wt2[r], v.x);      ffma2(ab2, wb2[r], v.x);
            ffma2(at2, wt2[r + 1], v.y);  ffma2(ab2, wb2[r + 1], v.y);
        }
        g_hXWt[l * 64 + j] = hsum2(at2);
        g_hXWb[l * 64 + j] = hsum2(ab2);
        __syncthreads();
    }
}

// ---------------------------------------------------------------------------
// Main: persistent, 2 nodes/warp, fused stages (R13 logic) + manual
// software pipelining: every matvec loop double-buffers its 4 LDS.128 loads
// (issue k4+1's loads BEFORE k4's FFMA2s) so LDS latency hides under compute
// and the fma/LSU pipes overlap instead of alternating. Also prefetches the
// next grp's neighbor int4s across iterations.
// ---------------------------------------------------------------------------
__global__ __launch_bounds__(256, 1) void ggcn_main_kernel(
    const int*   __restrict__ nbr,
    const float* __restrict__ g1w,
    const float* __restrict__ g1b,
    const float* __restrict__ fw,
    const float* __restrict__ fb,
    float*       __restrict__ out)
{
    __shared__ __align__(16) float s_v[8][2][6][64];   // [warp][node][vec][j]

    int warp = threadIdx.x >> 5;
    int t    = threadIdx.x & 31;

    // ---- prologue (once per block) ----
    u64 wlo[32], whi[32];
#pragma unroll
    for (int k2 = 0; k2 < 32; k2++) {
        wlo[k2] = pack2(g1w[(64 + 2 * k2) * 64 + t],
                        g1w[(64 + 2 * k2 + 1) * 64 + t]);
        whi[k2] = pack2(g1w[(64 + 2 * k2) * 64 + t + 32],
                        g1w[(64 + 2 * k2 + 1) * 64 + t + 32]);
    }
    float blo = g1b[t], bhi = g1b[t + 32];
    float fwl0 = fw[t * 2 + 0],        fwl1 = fw[t * 2 + 1];
    float fwh0 = fw[(t + 32) * 2 + 0], fwh1 = fw[(t + 32) * 2 + 1];
    float fb0 = fb[0], fb1 = fb[1];

    const int PA[6] = {0, 0, 0, 1, 1, 2};
    const int PB[6] = {1, 2, 3, 2, 3, 3};
    const int CP1[3] = {0, 1, 2};
    const int CP2[3] = {5, 4, 3};
    const int C1A[3] = {2, 1, 1};
    const int C1B[3] = {3, 3, 2};
    const int C2A[3] = {0, 0, 0};
    const int C2B[3] = {1, 2, 3};

    const int NGRP = L_NODES / 16;   // 1875

    // ---- neighbor prefetch for first iteration ----
    int4 nbA, nbB;
    {
        int l0f = blockIdx.x * 16 + warp * 2;
        nbA = ((const int4*)nbr)[l0f];
        nbB = ((const int4*)nbr)[l0f + 1];
    }

    for (int grp = blockIdx.x; grp < NGRP; grp += gridDim.x) {
        int l0 = grp * 16 + warp * 2;
        int l1 = l0 + 1;

        int niA[4] = {nbA.x, nbA.y, nbA.z, nbA.w};
        int niB[4] = {nbB.x, nbB.y, nbB.z, nbB.w};

        float Aib0l[4], Aib0h[4], Aib1l[4], Aib1h[4];
#pragma unroll
        for (int i = 0; i < 4; i++) {
            Aib0l[i] = g_hXWt[niA[i] * 64 + t]      + blo;
            Aib0h[i] = g_hXWt[niA[i] * 64 + t + 32] + bhi;
            Aib1l[i] = g_hXWt[niB[i] * 64 + t]      + blo;
            Aib1h[i] = g_hXWt[niB[i] * 64 + t + 32] + bhi;
        }
        float hx0l = g_hXWt[l0 * 64 + t], hx0h = g_hXWt[l0 * 64 + t + 32];
        float hx1l = g_hXWt[l1 * 64 + t], hx1h = g_hXWt[l1 * 64 + t + 32];

        // ---- pairs (B scoped; dies here) ----
        {
            float B0l[4], B0h[4], B1l[4], B1h[4];
#pragma unroll
            for (int i = 0; i < 4; i++) {
                B0l[i] = g_hXWb[niA[i] * 64 + t];
                B0h[i] = g_hXWb[niA[i] * 64 + t + 32];
                B1l[i] = g_hXWb[niB[i] * 64 + t];
                B1h[i] = g_hXWb[niB[i] * 64 + t + 32];
            }
#pragma unroll
            for (int p = 0; p < 6; p++) {
                int i0 = PA[p], i1 = PB[p];
                s_v[warp][0][p][t] =
                    0.5f * (fmaxf(Aib0l[i0] + B0l[i1], 0.0f) +
                            fmaxf(Aib0l[i1] + B0l[i0], 0.0f));
                s_v[warp][0][p][t + 32] =
                    0.5f * (fmaxf(Aib0h[i0] + B0h[i1], 0.0f) +
                            fmaxf(Aib0h[i1] + B0h[i0], 0.0f));
                s_v[warp][1][p][t] =
                    0.5f * (fmaxf(Aib1l[i0] + B1l[i1], 0.0f) +
                            fmaxf(Aib1l[i1] + B1l[i0], 0.0f));
                s_v[warp][1][p][t + 32] =
                    0.5f * (fmaxf(Aib1h[i0] + B1h[i1], 0.0f) +
                            fmaxf(Aib1h[i1] + B1h[i0], 0.0f));
            }
        }

        // ---- prefetch next iteration's neighbor indices (hidden under matvecs)
        {
            int ng = grp + gridDim.x;
            int safe = (ng < NGRP) ? ng : grp;
            int lp = safe * 16 + warp * 2;
            nbA = ((const int4*)nbr)[lp];
            nbB = ((const int4*)nbr)[lp + 1];
        }
        __syncwarp();

        // ---- fused PWb matvecs + triple accumulation (software-pipelined) ----
        float tr0l[4] = {0.f, 0.f, 0.f, 0.f}, tr0h[4] = {0.f, 0.f, 0.f, 0.f};
        float tr1l[4] = {0.f, 0.f, 0.f, 0.f}, tr1h[4] = {0.f, 0.f, 0.f, 0.f};
#pragma unroll
        for (int cp = 0; cp < 3; cp++) {
            int p = CP1[cp], q = CP2[cp];
            u64 a0l = 0ull, a0h = 0ull, a1l = 0ull, a1h = 0ull;
            u64 c0l = 0ull, c0h = 0ull, c1l = 0ull, c1h = 0ull;
            const ulonglong2* vP0 = (const ulonglong2*)s_v[warp][0][p];
            const ulonglong2* vQ0 = (const ulonglong2*)s_v[warp][0][q];
            const ulonglong2* vP1 = (const ulonglong2*)s_v[warp][1][p];
            const ulonglong2* vQ1 = (const ulonglong2*)s_v[warp][1][q];

            ulonglong2 cP0 = vP0[0], cQ0 = vQ0[0], cP1 = vP1[0], cQ1 = vQ1[0];
#pragma unroll
            for (int k4 = 0; k4 < 16; k4++) {
                ulonglong2 nP0, nQ0, nP1, nQ1;
                if (k4 < 15) {
                    nP0 = vP0[k4 + 1]; nQ0 = vQ0[k4 + 1];
                    nP1 = vP1[k4 + 1]; nQ1 = vQ1[k4 + 1];
                }
                int r = 2 * k4;
                ffma2(a0l, wlo[r], cP0.x);      ffma2(a0h, whi[r], cP0.x);
                ffma2(a0l, wlo[r + 1], cP0.y);  ffma2(a0h, whi[r + 1], cP0.y);
                ffma2(c0l, wlo[r], cQ0.x);      ffma2(c0h, whi[r], cQ0.x);
                ffma2(c0l, wlo[r + 1], cQ0.y);  ffma2(c0h, whi[r + 1], cQ0.y);
                ffma2(a1l, wlo[r], cP1.x);      ffma2(a1h, whi[r], cP1.x);
                ffma2(a1l, wlo[r + 1], cP1.y);  ffma2(a1h, whi[r + 1], cP1.y);
                ffma2(c1l, wlo[r], cQ1.x);      ffma2(c1h, whi[r], cQ1.x);
                ffma2(c1l, wlo[r + 1], cQ1.y);  ffma2(c1h, whi[r + 1], cQ1.y);
                if (k4 < 15) { cP0 = nP0; cQ0 = nQ0; cP1 = nP1; cQ1 = nQ1; }
            }
            float pw0l = hsum2(a0l), pw0h = hsum2(a0h);
            float qw0l = hsum2(c0l), qw0h = hsum2(c0h);
            float pw1l = hsum2(a1l), pw1h = hsum2(a1h);
            float qw1l = hsum2(c1l), qw1h = hsum2(c1h);

            int u = C1A[cp], v = C1B[cp];
            int x = C2A[cp], y = C2B[cp];
            tr0l[u] += fmaxf(Aib0l[v] + pw0l, 0.0f);
            tr0l[v] += fmaxf(Aib0l[u] + pw0l, 0.0f);
            tr0h[u] += fmaxf(Aib0h[v] + pw0h, 0.0f);
            tr0h[v] += fmaxf(Aib0h[u] + pw0h, 0.0f);
            tr0l[x] += fmaxf(Aib0l[y] + qw0l, 0.0f);
            tr0l[y] += fmaxf(Aib0l[x] + qw0l, 0.0f);
            tr0h[x] += fmaxf(Aib0h[y] + qw0h, 0.0f);
            tr0h[y] += fmaxf(Aib0h[x] + qw0h, 0.0f);
            tr1l[u] += fmaxf(Aib1l[v] + pw1l, 0.0f);
            tr1l[v] += fmaxf(Aib1l[u] + pw1l, 0.0f);
            tr1h[u] += fmaxf(Aib1h[v] + pw1h, 0.0f);
            tr1h[v] += fmaxf(Aib1h[u] + pw1h, 0.0f);
            tr1l[x] += fmaxf(Aib1l[y] + qw1l, 0.0f);
            tr1l[y] += fmaxf(Aib1l[x] + qw1l, 0.0f);
            tr1h[x] += fmaxf(Aib1h[y] + qw1h, 0.0f);
            tr1h[y] += fmaxf(Aib1h[x] + qw1h, 0.0f);
        }
        __syncwarp();

        // ---- stage triple vectors ----
#pragma unroll
        for (int m = 0; m < 4; m++) {
            s_v[warp][0][m][t]      = tr0l[m] * (1.0f / 3.0f);
            s_v[warp][0][m][t + 32] = tr0h[m] * (1.0f / 3.0f);
            s_v[warp][1][m][t]      = tr1l[m] * (1.0f / 3.0f);
            s_v[warp][1][m][t + 32] = tr1h[m] * (1.0f / 3.0f);
        }
        __syncwarp();

        // ---- fused TWb matvecs + quad accumulation (software-pipelined) ----
        float q0l = 0.f, q0h = 0.f, q1l = 0.f, q1h = 0.f;
#pragma unroll
        for (int m = 0; m < 4; m += 2) {
            u64 a0l = 0ull, a0h = 0ull, a1l = 0ull, a1h = 0ull;
            u64 c0l = 0ull, c0h = 0ull, c1l = 0ull, c1h = 0ull;
            const ulonglong2* v0A = (const ulonglong2*)s_v[warp][0][m];
            const ulonglong2* v1A = (const ulonglong2*)s_v[warp][0][m + 1];
            const ulonglong2* v0B = (const ulonglong2*)s_v[warp][1][m];
            const ulonglong2* v1B = (const ulonglong2*)s_v[warp][1][m + 1];

            ulonglong2 cVA = v0A[0], cUA = v1A[0], cVB = v0B[0], cUB = v1B[0];
#pragma unroll
            for (int k4 = 0; k4 < 16; k4++) {
                ulonglong2 nVA, nUA, nVB, nUB;
                if (k4 < 15) {
                    nVA = v0A[k4 + 1]; nUA = v1A[k4 + 1];
                    nVB = v0B[k4 + 1]; nUB = v1B[k4 + 1];
                }
                int r = 2 * k4;
                ffma2(a0l, wlo[r], cVA.x);      ffma2(a0h, whi[r], cVA.x);
                ffma2(a0l, wlo[r + 1], cVA.y);  ffma2(a0h, whi[r + 1], cVA.y);
                ffma2(a1l, wlo[r], cUA.x);      ffma2(a1h, whi[r], cUA.x);
                ffma2(a1l, wlo[r + 1], cUA.y);  ffma2(a1h, whi[r + 1], cUA.y);
                ffma2(c0l, wlo[r], cVB.x);      ffma2(c0h, whi[r], cVB.x);
                ffma2(c0l, wlo[r + 1], cVB.y);  ffma2(c0h, whi[r + 1], cVB.y);
                ffma2(c1l, wlo[r], cUB.x);      ffma2(c1h, whi[r], cUB.x);
                ffma2(c1l, wlo[r + 1], cUB.y);  ffma2(c1h, whi[r + 1], cUB.y);
                if (k4 < 15) { cVA = nVA; cUA = nUA; cVB = nVB; cUB = nUB; }
            }
            q0l += fmaxf(Aib0l[m] + hsum2(a0l), 0.0f)
                 + fmaxf(Aib0l[m + 1] + hsum2(a1l), 0.0f);
            q0h += fmaxf(Aib0h[m] + hsum2(a0h), 0.0f)
                 + fmaxf(Aib0h[m + 1] + hsum2(a1h), 0.0f);
            q1l += fmaxf(Aib1l[m] + hsum2(c0l), 0.0f)
                 + fmaxf(Aib1l[m + 1] + hsum2(c1l), 0.0f);
            q1h += fmaxf(Aib1h[m] + hsum2(c0h), 0.0f)
                 + fmaxf(Aib1h[m + 1] + hsum2(c1h), 0.0f);
        }
        __syncwarp();

        // ---- E vector ----
        s_v[warp][0][0][t]      = fmaxf(q0l * 0.25f, 0.0f);
        s_v[warp][0][0][t + 32] = fmaxf(q0h * 0.25f, 0.0f);
        s_v[warp][1][0][t]      = fmaxf(q1l * 0.25f, 0.0f);
        s_v[warp][1][0][t + 32] = fmaxf(q1h * 0.25f, 0.0f);
        __syncwarp();

        // ---- E2 = relu(hxwt + E@Wb + b) (software-pipelined) ----
        u64 e0l = 0ull, e0h = 0ull, e1l = 0ull, e1h = 0ull;
        {
            const ulonglong2* vA = (const ulonglong2*)s_v[warp][0][0];
            const ulonglong2* vB = (const ulonglong2*)s_v[warp][1][0];
            ulonglong2 cA = vA[0], cB = vB[0];
#pragma unroll
            for (int k4 = 0; k4 < 16; k4++) {
                ulonglong2 nA, nB;
                if (k4 < 15) { nA = vA[k4 + 1]; nB = vB[k4 + 1]; }
                int r = 2 * k4;
                ffma2(e0l, wlo[r], cA.x);      ffma2(e0h, whi[r], cA.x);
                ffma2(e0l, wlo[r + 1], cA.y);  ffma2(e0h, whi[r + 1], cA.y);
                ffma2(e1l, wlo[r], cB.x);      ffma2(e1h, whi[r], cB.x);
                ffma2(e1l, wlo[r + 1], cB.y);  ffma2(e1h, whi[r + 1], cB.y);
                if (k4 < 15) { cA = nA; cB = nB; }
            }
        }
        float E20l = fmaxf(hx0l + hsum2(e0l) + blo, 0.0f);
        float E20h = fmaxf(hx0h + hsum2(e0h) + bhi, 0.0f);
        float E21l = fmaxf(hx1l + hsum2(e1l) + blo, 0.0f);
        float E21h = fmaxf(hx1h + hsum2(e1h) + bhi, 0.0f);

        // ---- readout head ----
        float p0 = E20l * fwl0 + E20h * fwh0;
        float p1 = E20l * fwl1 + E20h * fwh1;
        float r0 = E21l * fwl0 + E21h * fwh0;
        float r1 = E21l * fwl1 + E21h * fwh1;
#pragma unroll
        for (int off = 16; off > 0; off >>= 1) {
            p0 += __shfl_xor_sync(0xffffffffu, p0, off);
            p1 += __shfl_xor_sync(0xffffffffu, p1, off);
            r0 += __shfl_xor_sync(0xffffffffu, r0, off);
            r1 += __shfl_xor_sync(0xffffffffu, r1, off);
        }
        if (t == 0) {
            float2 oA = {p0 + fb0, p1 + fb1};
            float2 oB = {r0 + fb0, r1 + fb1};
            *(float2*)(out + l0 * 2) = oA;
            *(float2*)(out + l1 * 2) = oB;
        }
        __syncwarp();   // protect s_v reuse across loop iterations
    }
}

// ---------------------------------------------------------------------------
// kernel_launch: graph-capturable, allocation-free.
// Inputs: X, neighbors, h1_w, h1_b, g1_w, g1_b, final_w, final_b
// ---------------------------------------------------------------------------
extern "C" void kernel_launch(void* const* d_in, const int* in_sizes, int n_in,
                              void* d_out, int out_size)
{
    const float* X    = (const float*)d_in[0];
    const int*   nbr  = (const int*)  d_in[1];
    const float* h1w  = (const float*)d_in[2];
    const float* h1b  = (const float*)d_in[3];
    const float* g1w  = (const float*)d_in[4];
    const float* g1b  = (const float*)d_in[5];
    const float* fw   = (const float*)d_in[6];
    const float* fb   = (const float*)d_in[7];
    float* out = (float*)d_out;

    (void)in_sizes; (void)n_in; (void)out_size;

    prep_kernel<<<296, 256>>>(X, h1w, h1b, g1w);
    ggcn_main_kernel<<<148, 256>>>(nbr, g1w, g1b, fw, fb, out);
}